// round 2
// baseline (speedup 1.0000x reference)
#include <cuda_runtime.h>
#include <cuda_bf16.h>

#define LL 4
#define CC 128
#define HH 240
#define WW 480
#define PP (HH*WW)      // 115200
#define RR 8
#define KK 36
#define CH 64           // C/2
#define NW (CC*RR + RR*KK)  // 1312

// Scratch (device globals; no allocation allowed)
__device__ float g_ctx[LL*CC];
__device__ __align__(16) float g_W1[LL*CC*RR];   // gain-folded W1
__device__ float g_W2[LL*RR*KK];
__device__ __align__(16) float g_Z[LL*RR*PP];    // 14.7 MB

// ---------------------------------------------------------------------------
// Kernel 1: per-(l,c) mean over H*W.  grid = L*C blocks, 256 threads.
// ---------------------------------------------------------------------------
__global__ void mean_kernel(const float* __restrict__ x) {
    int row = blockIdx.x;                       // l*C + c
    const float4* xr = (const float4*)(x + (size_t)row * PP);
    float s = 0.f;
    for (int i = threadIdx.x; i < PP/4; i += blockDim.x) {
        float4 v = xr[i];
        s += (v.x + v.y) + (v.z + v.w);
    }
    #pragma unroll
    for (int o = 16; o; o >>= 1) s += __shfl_xor_sync(0xffffffffu, s, o);
    __shared__ float red[8];
    int warp = threadIdx.x >> 5;
    if ((threadIdx.x & 31) == 0) red[warp] = s;
    __syncthreads();
    if (threadIdx.x == 0) {
        float t = 0.f;
        #pragma unroll
        for (int w = 0; w < 8; w++) t += red[w];
        g_ctx[row] = t * (1.0f / (float)PP);
    }
}

// ---------------------------------------------------------------------------
// Kernel 2: hypernet.  One block, 256 threads.
//   h = silu(ctx @ Wa + ba)           (4,64)
//   wf = h @ Wb + bb                  (4,1312)
//   W1[l,c,r] = gain[c]*wf[..c*8+r],  W2[l,r,k] = wf[..1024+r*36+k]
// ---------------------------------------------------------------------------
__global__ void hyper_kernel(const float* __restrict__ Wa, const float* __restrict__ ba,
                             const float* __restrict__ Wb, const float* __restrict__ bb,
                             const float* __restrict__ gain) {
    __shared__ float ctx[LL*CC];
    __shared__ float h[LL*CH];
    int t = threadIdx.x;
    for (int i = t; i < LL*CC; i += 256) ctx[i] = g_ctx[i];
    __syncthreads();
    {   // 256 threads == 4*64 h-outputs, one each
        int l = t >> 6, j = t & 63;
        float acc = ba[j];
        #pragma unroll 8
        for (int i = 0; i < CC; i++) acc += ctx[l*CC + i] * Wa[i*CH + j];
        h[t] = acc / (1.0f + expf(-acc));   // silu
    }
    __syncthreads();
    for (int idx = t; idx < LL*NW; idx += 256) {
        int l = idx / NW, j = idx - l*NW;
        float acc = bb[j];
        #pragma unroll 8
        for (int i = 0; i < CH; i++) acc += h[l*CH + i] * Wb[i*NW + j];
        if (j < CC*RR) {
            int c = j >> 3, r = j & 7;
            g_W1[(l*CC + c)*RR + r] = gain[c] * acc;
        } else {
            g_W2[l*RR*KK + (j - CC*RR)] = acc;  // [l][r][k], r*KK+k
        }
    }
}

// ---------------------------------------------------------------------------
// Kernel 3: Z[l,r,p] = sum_k W2[l,r,k] * Y[k,p].  2 pixels/thread (float2).
// grid = PP/512 = 225 blocks, 256 threads.
// ---------------------------------------------------------------------------
__global__ void z_kernel(const float* __restrict__ Y) {
    __shared__ float W2s[LL*RR*KK];
    int t = threadIdx.x;
    for (int i = t; i < LL*RR*KK; i += 256) W2s[i] = g_W2[i];
    __syncthreads();
    int p2 = blockIdx.x * 256 + t;          // float2 index, < PP/2
    const float2* Y2 = (const float2*)Y;
    float2 acc[LL*RR];
    #pragma unroll
    for (int lr = 0; lr < LL*RR; lr++) { acc[lr].x = 0.f; acc[lr].y = 0.f; }
    for (int k = 0; k < KK; k++) {
        float2 y = Y2[k*(PP/2) + p2];
        #pragma unroll
        for (int lr = 0; lr < LL*RR; lr++) {
            float w = W2s[lr*KK + k];
            acc[lr].x = fmaf(w, y.x, acc[lr].x);
            acc[lr].y = fmaf(w, y.y, acc[lr].y);
        }
    }
    float2* Z2 = (float2*)g_Z;
    #pragma unroll
    for (int lr = 0; lr < LL*RR; lr++) Z2[lr*(PP/2) + p2] = acc[lr];
}

// ---------------------------------------------------------------------------
// Kernel 4: out[l,c,p] = x[l,c,p] + sum_r W1g[l,c,r] * Z[l,r,p]
// grid = (ceil(PP/4/256), L), 256 threads; 4 pixels/thread (float4).
// ---------------------------------------------------------------------------
__device__ __forceinline__ void fma4(float4& a, float w, const float4& z) {
    a.x = fmaf(w, z.x, a.x);
    a.y = fmaf(w, z.y, a.y);
    a.z = fmaf(w, z.z, a.z);
    a.w = fmaf(w, z.w, a.w);
}

__global__ void final_kernel(const float* __restrict__ x, float* __restrict__ out) {
    int l = blockIdx.y;
    __shared__ float4 W1s[CC*2];            // [c][0..1] -> 8 r values
    int t = threadIdx.x;
    const float4* w1g = (const float4*)(g_W1 + l*CC*RR);
    for (int i = t; i < CC*2; i += 256) W1s[i] = w1g[i];
    __syncthreads();
    int p4 = blockIdx.x * 256 + t;
    if (p4 >= PP/4) return;
    float4 z[RR];
    const float4* Z4 = (const float4*)g_Z;
    #pragma unroll
    for (int r = 0; r < RR; r++) z[r] = Z4[(l*RR + r)*(PP/4) + p4];
    const float4* x4 = (const float4*)x;
    float4* o4 = (float4*)out;
    size_t base = (size_t)l * CC * (PP/4) + p4;
    #pragma unroll 4
    for (int c = 0; c < CC; c++) {
        float4 a = x4[base + (size_t)c*(PP/4)];
        float4 w0 = W1s[c*2], w1 = W1s[c*2 + 1];
        fma4(a, w0.x, z[0]); fma4(a, w0.y, z[1]);
        fma4(a, w0.z, z[2]); fma4(a, w0.w, z[3]);
        fma4(a, w1.x, z[4]); fma4(a, w1.y, z[5]);
        fma4(a, w1.z, z[6]); fma4(a, w1.w, z[7]);
        o4[base + (size_t)c*(PP/4)] = a;
    }
}

// ---------------------------------------------------------------------------
extern "C" void kernel_launch(void* const* d_in, const int* in_sizes, int n_in,
                              void* d_out, int out_size) {
    const float* x    = (const float*)d_in[0];
    const float* Wa   = (const float*)d_in[1];
    const float* ba   = (const float*)d_in[2];
    const float* Wb   = (const float*)d_in[3];
    const float* bb   = (const float*)d_in[4];
    const float* gain = (const float*)d_in[5];
    const float* Y    = (const float*)d_in[6];
    float* out = (float*)d_out;

    mean_kernel<<<LL*CC, 256>>>(x);
    hyper_kernel<<<1, 256>>>(Wa, ba, Wb, bb, gain);
    z_kernel<<<PP/512, 256>>>(Y);
    dim3 g((PP/4 + 255)/256, LL);
    final_kernel<<<g, 256>>>(x, out);
}

// round 5
// speedup vs baseline: 1.0266x; 1.0266x over previous
#include <cuda_runtime.h>
#include <cuda_bf16.h>

#define LL 4
#define CC 128
#define HH 240
#define WW 480
#define PP (HH*WW)      // 115200
#define RR 8
#define KK 36
#define CH 64           // C/2
#define NW (CC*RR + RR*KK)  // 1312
#define MSPLIT 4        // mean partial splits per row

// Scratch (device globals; no allocation allowed)
__device__ float g_part[LL*CC*MSPLIT];
__device__ __align__(16) float g_W1[LL*CC*RR];   // gain-folded W1
__device__ float g_W2[LL*RR*KK];
__device__ __align__(16) float g_Z[LL*RR*PP];    // 14.7 MB

// ---------------------------------------------------------------------------
// Kernel 1: partial sums over H*W.  grid = L*C*MSPLIT blocks, 256 threads.
// Each block sums PP/MSPLIT = 28800 floats (7200 float4).
// ---------------------------------------------------------------------------
__global__ void mean_kernel(const float* __restrict__ x) {
    int row   = blockIdx.x >> 2;            // l*C + c
    int split = blockIdx.x & 3;
    const int n4 = PP / 4 / MSPLIT;         // 7200 float4 per split
    const float4* xr = (const float4*)(x + (size_t)row * PP) + split * n4;
    float s0 = 0.f, s1 = 0.f;
    // 2 float4 in flight per iteration, 256 threads -> stride 512
    int i = threadIdx.x;
    for (; i + 256 < n4; i += 512) {
        float4 a = xr[i];
        float4 b = xr[i + 256];
        s0 += (a.x + a.y) + (a.z + a.w);
        s1 += (b.x + b.y) + (b.z + b.w);
    }
    if (i < n4) {
        float4 a = xr[i];
        s0 += (a.x + a.y) + (a.z + a.w);
    }
    float s = s0 + s1;
    #pragma unroll
    for (int o = 16; o; o >>= 1) s += __shfl_xor_sync(0xffffffffu, s, o);
    __shared__ float red[8];
    int warp = threadIdx.x >> 5;
    if ((threadIdx.x & 31) == 0) red[warp] = s;
    __syncthreads();
    if (threadIdx.x == 0) {
        float t = 0.f;
        #pragma unroll
        for (int w = 0; w < 8; w++) t += red[w];
        g_part[row * MSPLIT + split] = t;
    }
}

// ---------------------------------------------------------------------------
// Kernel 2: hypernet.  One block, 256 threads.
//   ctx = reduce(partials)/PP
//   h = silu(ctx @ Wa + ba)           (4,64)
//   wf = h @ Wb + bb                  (4,1312)
//   W1[l,c,r] = gain[c]*wf[..c*8+r],  W2[l,r,k] = wf[..1024+r*36+k]
// ---------------------------------------------------------------------------
__global__ void hyper_kernel(const float* __restrict__ Wa, const float* __restrict__ ba,
                             const float* __restrict__ Wb, const float* __restrict__ bb,
                             const float* __restrict__ gain) {
    __shared__ float ctx[LL*CC];
    __shared__ float h[LL*CH];
    int t = threadIdx.x;
    for (int i = t; i < LL*CC; i += 256) {
        float s = g_part[i*MSPLIT] + g_part[i*MSPLIT+1]
                + g_part[i*MSPLIT+2] + g_part[i*MSPLIT+3];
        ctx[i] = s * (1.0f / (float)PP);
    }
    __syncthreads();
    {   // 256 threads == 4*64 h-outputs, one each
        int l = t >> 6, j = t & 63;
        float acc = ba[j];
        #pragma unroll 8
        for (int i = 0; i < CC; i++) acc += ctx[l*CC + i] * Wa[i*CH + j];
        h[t] = acc / (1.0f + expf(-acc));   // silu
    }
    __syncthreads();
    for (int idx = t; idx < LL*NW; idx += 256) {
        int l = idx / NW, j = idx - l*NW;
        float acc = bb[j];
        #pragma unroll 8
        for (int i = 0; i < CH; i++) acc += h[l*CH + i] * Wb[i*NW + j];
        if (j < CC*RR) {
            int c = j >> 3, r = j & 7;
            g_W1[(l*CC + c)*RR + r] = gain[c] * acc;
        } else {
            g_W2[l*RR*KK + (j - CC*RR)] = acc;  // [l][r][k], r*KK+k
        }
    }
}

// ---------------------------------------------------------------------------
// Kernel 3: Z[l,r,p] = sum_k W2[l,r,k] * Y[k,p].  2 pixels/thread (float2).
// grid = PP/512 = 225 blocks, 256 threads.
// ---------------------------------------------------------------------------
__global__ void z_kernel(const float* __restrict__ Y) {
    __shared__ float W2s[LL*RR*KK];
    int t = threadIdx.x;
    for (int i = t; i < LL*RR*KK; i += 256) W2s[i] = g_W2[i];
    __syncthreads();
    int p2 = blockIdx.x * 256 + t;          // float2 index, < PP/2
    const float2* Y2 = (const float2*)Y;
    float2 acc[LL*RR];
    #pragma unroll
    for (int lr = 0; lr < LL*RR; lr++) { acc[lr].x = 0.f; acc[lr].y = 0.f; }
    for (int k = 0; k < KK; k++) {
        float2 y = Y2[k*(PP/2) + p2];
        #pragma unroll
        for (int lr = 0; lr < LL*RR; lr++) {
            float w = W2s[lr*KK + k];
            acc[lr].x = fmaf(w, y.x, acc[lr].x);
            acc[lr].y = fmaf(w, y.y, acc[lr].y);
        }
    }
    float2* Z2 = (float2*)g_Z;
    #pragma unroll
    for (int lr = 0; lr < LL*RR; lr++) Z2[lr*(PP/2) + p2] = acc[lr];
}

// ---------------------------------------------------------------------------
// Kernel 4: out[l,c,p] = x[l,c,p] + sum_r W1g[l,c,r] * Z[l,r,p]
// grid = (ceil(PP/4/256), L), 256 threads; 4 pixels/thread (float4).
// c-loop unrolled x8 for deep MLP (8 outstanding LDG.128 per thread).
// ---------------------------------------------------------------------------
__device__ __forceinline__ void fma4(float4& a, float w, const float4& z) {
    a.x = fmaf(w, z.x, a.x);
    a.y = fmaf(w, z.y, a.y);
    a.z = fmaf(w, z.z, a.z);
    a.w = fmaf(w, z.w, a.w);
}

__global__ __launch_bounds__(256) void final_kernel(const float* __restrict__ x,
                                                    float* __restrict__ out) {
    int l = blockIdx.y;
    __shared__ float4 W1s[CC*2];            // [c][0..1] -> 8 r values
    int t = threadIdx.x;
    const float4* w1g = (const float4*)(g_W1 + l*CC*RR);
    for (int i = t; i < CC*2; i += 256) W1s[i] = w1g[i];
    __syncthreads();
    int p4 = blockIdx.x * 256 + t;
    if (p4 >= PP/4) return;
    float4 z[RR];
    const float4* Z4 = (const float4*)g_Z;
    #pragma unroll
    for (int r = 0; r < RR; r++) z[r] = Z4[(l*RR + r)*(PP/4) + p4];
    const float4* x4 = (const float4*)x;
    float4* o4 = (float4*)out;
    size_t base = (size_t)l * CC * (PP/4) + p4;
    #pragma unroll 8
    for (int c = 0; c < CC; c++) {
        float4 a = x4[base + (size_t)c*(PP/4)];
        float4 w0 = W1s[c*2], w1 = W1s[c*2 + 1];
        fma4(a, w0.x, z[0]); fma4(a, w0.y, z[1]);
        fma4(a, w0.z, z[2]); fma4(a, w0.w, z[3]);
        fma4(a, w1.x, z[4]); fma4(a, w1.y, z[5]);
        fma4(a, w1.z, z[6]); fma4(a, w1.w, z[7]);
        o4[base + (size_t)c*(PP/4)] = a;
    }
}

// ---------------------------------------------------------------------------
extern "C" void kernel_launch(void* const* d_in, const int* in_sizes, int n_in,
                              void* d_out, int out_size) {
    const float* x    = (const float*)d_in[0];
    const float* Wa   = (const float*)d_in[1];
    const float* ba   = (const float*)d_in[2];
    const float* Wb   = (const float*)d_in[3];
    const float* bb   = (const float*)d_in[4];
    const float* gain = (const float*)d_in[5];
    const float* Y    = (const float*)d_in[6];
    float* out = (float*)d_out;

    mean_kernel<<<LL*CC*MSPLIT, 256>>>(x);
    hyper_kernel<<<1, 256>>>(Wa, ba, Wb, bb, gain);
    z_kernel<<<PP/512, 256>>>(Y);
    dim3 g((PP/4 + 255)/256, LL);
    final_kernel<<<g, 256>>>(x, out);
}

// round 8
// speedup vs baseline: 1.5505x; 1.5103x over previous
#include <cuda_runtime.h>
#include <cuda_bf16.h>

#define LL 4
#define CC 128
#define HH 240
#define WW 480
#define PP (HH*WW)      // 115200
#define RR 8
#define KK 36
#define CH 64           // C/2
#define NW (CC*RR + RR*KK)  // 1312
#define MSPLIT 4        // mean partial splits per row

// Scratch (device globals; no allocation allowed)
__device__ float g_part[LL*CC*MSPLIT];
__device__ float g_h[LL*CH];
__device__ __align__(16) float g_W1[LL*CC*RR];   // gain-folded W1
__device__ float g_W2[LL*RR*KK];

// ---------------------------------------------------------------------------
// Kernel 1: partial sums over H*W.  grid = L*C*MSPLIT blocks, 256 threads.
// ---------------------------------------------------------------------------
__global__ void mean_kernel(const float* __restrict__ x) {
    int row   = blockIdx.x >> 2;            // l*C + c
    int split = blockIdx.x & 3;
    const int n4 = PP / 4 / MSPLIT;         // 7200 float4 per split
    const float4* xr = (const float4*)(x + (size_t)row * PP) + split * n4;
    float s0 = 0.f, s1 = 0.f;
    int i = threadIdx.x;
    for (; i + 256 < n4; i += 512) {
        float4 a = xr[i];
        float4 b = xr[i + 256];
        s0 += (a.x + a.y) + (a.z + a.w);
        s1 += (b.x + b.y) + (b.z + b.w);
    }
    if (i < n4) {
        float4 a = xr[i];
        s0 += (a.x + a.y) + (a.z + a.w);
    }
    float s = s0 + s1;
    #pragma unroll
    for (int o = 16; o; o >>= 1) s += __shfl_xor_sync(0xffffffffu, s, o);
    __shared__ float red[8];
    int warp = threadIdx.x >> 5;
    if ((threadIdx.x & 31) == 0) red[warp] = s;
    __syncthreads();
    if (threadIdx.x == 0) {
        float t = 0.f;
        #pragma unroll
        for (int w = 0; w < 8; w++) t += red[w];
        g_part[row * MSPLIT + split] = t;
    }
}

// ---------------------------------------------------------------------------
// Kernel 2a: ctx reduce + first GEMM + silu.  One block, 256 threads.
//   h[l,j] = silu(ctx[l,:] @ Wa[:,j] + ba[j]),  256 outputs = 1/thread
// ---------------------------------------------------------------------------
__global__ void hyper1_kernel(const float* __restrict__ Wa, const float* __restrict__ ba) {
    __shared__ float ctx[LL*CC];
    int t = threadIdx.x;
    for (int i = t; i < LL*CC; i += 256) {
        float s = g_part[i*MSPLIT] + g_part[i*MSPLIT+1]
                + g_part[i*MSPLIT+2] + g_part[i*MSPLIT+3];
        ctx[i] = s * (1.0f / (float)PP);
    }
    __syncthreads();
    int l = t >> 6, j = t & 63;
    float acc = ba[j];
    #pragma unroll 16
    for (int i = 0; i < CC; i++) acc += ctx[l*CC + i] * Wa[i*CH + j];
    g_h[t] = acc / (1.0f + expf(-acc));   // silu
}

// ---------------------------------------------------------------------------
// Kernel 2b: second GEMM, parallel.  grid = ceil(L*NW/256) = 21 blocks.
//   wf[l,j] = h[l,:] @ Wb[:,j] + bb[j]  -> W1 (gain-folded) / W2
// Coalesced Wb loads (consecutive threads -> consecutive j).
// ---------------------------------------------------------------------------
__global__ void hyper2_kernel(const float* __restrict__ Wb, const float* __restrict__ bb,
                              const float* __restrict__ gain) {
    __shared__ float h[LL*CH];
    int t = threadIdx.x;
    if (t < LL*CH) h[t] = g_h[t];
    __syncthreads();
    int idx = blockIdx.x * 256 + t;
    if (idx >= LL*NW) return;
    int l = idx / NW, j = idx - l*NW;
    float acc = bb[j];
    #pragma unroll 16
    for (int i = 0; i < CH; i++) acc += h[l*CH + i] * Wb[i*NW + j];
    if (j < CC*RR) {
        int c = j >> 3, r = j & 7;
        g_W1[(l*CC + c)*RR + r] = gain[c] * acc;
    } else {
        g_W2[l*RR*KK + (j - CC*RR)] = acc;  // [l][r][k], r*KK+k
    }
}

// ---------------------------------------------------------------------------
// Kernel 3: fused z + bias-add.
//   z[r] = sum_k W2[l,r,k] * Y[k,p]        (per-thread, Y from L2)
//   out[l,c,p] = x[l,c,p] + sum_r W1g[l,c,r] * z[r]
// grid = (ceil(PP/4/256), L), 256 threads; 4 pixels/thread (float4).
// ---------------------------------------------------------------------------
__device__ __forceinline__ void fma4(float4& a, float w, const float4& z) {
    a.x = fmaf(w, z.x, a.x);
    a.y = fmaf(w, z.y, a.y);
    a.z = fmaf(w, z.z, a.z);
    a.w = fmaf(w, z.w, a.w);
}

__global__ __launch_bounds__(256) void final_kernel(const float* __restrict__ x,
                                                    const float* __restrict__ Y,
                                                    float* __restrict__ out) {
    int l = blockIdx.y;
    __shared__ float4 W1s[CC*2];            // 256 float4 = [c][r0..3],[c][r4..7]
    __shared__ float  W2s[RR*KK];
    int t = threadIdx.x;
    const float4* w1g = (const float4*)(g_W1 + l*CC*RR);
    W1s[t] = w1g[t];                        // 256 threads cover all 256 entries
    if (t < RR*KK) W2s[t] = g_W2[l*RR*KK + t];
    __syncthreads();
    int p4 = blockIdx.x * 256 + t;
    if (p4 >= PP/4) return;

    // z[r] = sum_k W2[r,k] * Y[k, 4 pixels]
    float4 z[RR];
    #pragma unroll
    for (int r = 0; r < RR; r++) { z[r].x = z[r].y = z[r].z = z[r].w = 0.f; }
    const float4* Y4 = (const float4*)Y;
    #pragma unroll 4
    for (int k = 0; k < KK; k++) {
        float4 y = Y4[k*(PP/4) + p4];
        #pragma unroll
        for (int r = 0; r < RR; r++) fma4(z[r], W2s[r*KK + k], y);
    }

    const float4* x4 = (const float4*)x;
    float4* o4 = (float4*)out;
    size_t base = (size_t)l * CC * (PP/4) + p4;
    #pragma unroll 8
    for (int c = 0; c < CC; c++) {
        float4 a = x4[base + (size_t)c*(PP/4)];
        float4 w0 = W1s[c*2], w1 = W1s[c*2 + 1];
        fma4(a, w0.x, z[0]); fma4(a, w0.y, z[1]);
        fma4(a, w0.z, z[2]); fma4(a, w0.w, z[3]);
        fma4(a, w1.x, z[4]); fma4(a, w1.y, z[5]);
        fma4(a, w1.z, z[6]); fma4(a, w1.w, z[7]);
        o4[base + (size_t)c*(PP/4)] = a;
    }
}

// ---------------------------------------------------------------------------
extern "C" void kernel_launch(void* const* d_in, const int* in_sizes, int n_in,
                              void* d_out, int out_size) {
    const float* x    = (const float*)d_in[0];
    const float* Wa   = (const float*)d_in[1];
    const float* ba   = (const float*)d_in[2];
    const float* Wb   = (const float*)d_in[3];
    const float* bb   = (const float*)d_in[4];
    const float* gain = (const float*)d_in[5];
    const float* Y    = (const float*)d_in[6];
    float* out = (float*)d_out;

    mean_kernel<<<LL*CC*MSPLIT, 256>>>(x);
    hyper1_kernel<<<1, 256>>>(Wa, ba);
    hyper2_kernel<<<(LL*NW + 255)/256, 256>>>(Wb, bb, gain);
    dim3 g((PP/4 + 255)/256, LL);
    final_kernel<<<g, 256>>>(x, Y, out);
}